// round 5
// baseline (speedup 1.0000x reference)
#include <cuda_runtime.h>
#include <cstdint>

#define BB 32
#define TT 1024
#define CC 512
#define DD 256
#define UU 256
#define FOURU 1024
#define MTOT (BB*TT)

__device__ float g_xin[(size_t)MTOT * DD];
__device__ float g_xz [(size_t)MTOT * FOURU];
__device__ float g_hs [(size_t)MTOT * UU];

// ---------------- f32x2 helpers ----------------
__device__ __forceinline__ unsigned long long fma2(unsigned long long a,
                                                   unsigned long long b,
                                                   unsigned long long c) {
    unsigned long long d;
    asm("fma.rn.f32x2 %0, %1, %2, %3;" : "=l"(d) : "l"(a), "l"(b), "l"(c));
    return d;
}
__device__ __forceinline__ unsigned long long pack2(float lo, float hi) {
    unsigned long long d;
    asm("mov.b64 %0, {%1, %2};" : "=l"(d) : "r"(__float_as_uint(lo)), "r"(__float_as_uint(hi)));
    return d;
}
__device__ __forceinline__ float lo32(unsigned long long v) {
    return __uint_as_float((unsigned)(v & 0xffffffffull));
}
__device__ __forceinline__ float hi32(unsigned long long v) {
    return __uint_as_float((unsigned)(v >> 32));
}

// ---------------------------------------------------------------------------
// GEMM with bias, f32x2 inner product. BM=128, BN=64, BK=16, 256 thr, 8x4.
// ---------------------------------------------------------------------------
__global__ void __launch_bounds__(256)
gemm_bias_kernel(const float* __restrict__ A, const float* __restrict__ B,
                 const float* __restrict__ bias, float* __restrict__ C,
                 int M, int N, int K)
{
    __shared__ float As[16][132];
    __shared__ float Bs[16][64];

    const int tid = threadIdx.x;
    const int tx = tid & 15;
    const int ty = tid >> 4;
    const int bm = blockIdx.y * 128;
    const int bn = blockIdx.x * 64;

    unsigned long long acc2[4][4];
    #pragma unroll
    for (int i = 0; i < 4; i++)
        #pragma unroll
        for (int j = 0; j < 4; j++) acc2[i][j] = 0ull;

    for (int k0 = 0; k0 < K; k0 += 16) {
        #pragma unroll
        for (int l = 0; l < 2; l++) {
            int id = tid + 256 * l;
            int r  = id >> 2;
            int c4 = id & 3;
            float4 v = *(const float4*)&A[(size_t)(bm + r) * K + k0 + c4 * 4];
            As[c4*4+0][r] = v.x;
            As[c4*4+1][r] = v.y;
            As[c4*4+2][r] = v.z;
            As[c4*4+3][r] = v.w;
        }
        {
            int r  = tid >> 4;
            int c4 = tid & 15;
            float4 v = *(const float4*)&B[(size_t)(k0 + r) * N + bn + c4 * 4];
            *(float4*)&Bs[r][c4 * 4] = v;
        }
        __syncthreads();

        #pragma unroll
        for (int kk = 0; kk < 16; kk++) {
            const ulonglong2* ap = reinterpret_cast<const ulonglong2*>(&As[kk][ty * 8]);
            ulonglong2 aA = ap[0];
            ulonglong2 aB = ap[1];
            float4 bf = *(const float4*)&Bs[kk][tx * 4];
            unsigned long long bd[4];
            bd[0] = pack2(bf.x, bf.x);
            bd[1] = pack2(bf.y, bf.y);
            bd[2] = pack2(bf.z, bf.z);
            bd[3] = pack2(bf.w, bf.w);
            #pragma unroll
            for (int j = 0; j < 4; j++) {
                acc2[0][j] = fma2(aA.x, bd[j], acc2[0][j]);
                acc2[1][j] = fma2(aA.y, bd[j], acc2[1][j]);
                acc2[2][j] = fma2(aB.x, bd[j], acc2[2][j]);
                acc2[3][j] = fma2(aB.y, bd[j], acc2[3][j]);
            }
        }
        __syncthreads();
    }

    float bv[4];
    #pragma unroll
    for (int j = 0; j < 4; j++) bv[j] = bias[bn + tx * 4 + j];

    #pragma unroll
    for (int ip = 0; ip < 4; ip++) {
        float4 o0, o1;
        o0.x = lo32(acc2[ip][0]) + bv[0];
        o0.y = lo32(acc2[ip][1]) + bv[1];
        o0.z = lo32(acc2[ip][2]) + bv[2];
        o0.w = lo32(acc2[ip][3]) + bv[3];
        o1.x = hi32(acc2[ip][0]) + bv[0];
        o1.y = hi32(acc2[ip][1]) + bv[1];
        o1.z = hi32(acc2[ip][2]) + bv[2];
        o1.w = hi32(acc2[ip][3]) + bv[3];
        *(float4*)&C[(size_t)(bm + ty * 8 + ip * 2 + 0) * N + bn + tx * 4] = o0;
        *(float4*)&C[(size_t)(bm + ty * 8 + ip * 2 + 1) * N + bn + tx * 4] = o1;
    }
}

// ---------------------------------------------------------------------------
// LSTM: 16 clusters x 8 CTAs x 256 threads.
// thread: gc = tid>>1 in [0,128), kh = tid&1 (k-half of 128).
// gc -> unit_loc = gc>>2, gate = gc&3. Weights 128 fp32 = 64 f32x2 regs.
// h exchange: smem staging + 16x 128B cluster bulk copies w/ mbarrier tx.
// ---------------------------------------------------------------------------
__device__ __forceinline__ uint32_t mapa_(uint32_t addr, uint32_t rank) {
    uint32_t r;
    asm("mapa.shared::cluster.u32 %0, %1, %2;" : "=r"(r) : "r"(addr), "r"(rank));
    return r;
}
__device__ __forceinline__ void mbar_init(uint32_t addr, uint32_t cnt) {
    asm volatile("mbarrier.init.shared.b64 [%0], %1;" :: "r"(addr), "r"(cnt) : "memory");
}
__device__ __forceinline__ void mbar_expect_tx(uint32_t addr, uint32_t tx) {
    asm volatile("mbarrier.arrive.expect_tx.shared.b64 _, [%0], %1;"
                 :: "r"(addr), "r"(tx) : "memory");
}
__device__ __forceinline__ void mbar_wait(uint32_t addr, uint32_t parity) {
    uint32_t done;
    asm volatile("{\n\t.reg .pred p;\n\t"
                 "mbarrier.try_wait.parity.acquire.cta.shared::cta.b64 p, [%1], %2, 0x989680;\n\t"
                 "selp.b32 %0, 1, 0, p;\n\t}"
                 : "=r"(done) : "r"(addr), "r"(parity) : "memory");
    while (!done) {
        asm volatile("{\n\t.reg .pred p;\n\t"
                     "mbarrier.try_wait.parity.acquire.cta.shared::cta.b64 p, [%1], %2, 0x989680;\n\t"
                     "selp.b32 %0, 1, 0, p;\n\t}"
                     : "=r"(done) : "r"(addr), "r"(parity) : "memory");
    }
}
__device__ __forceinline__ void bulk_smem_cluster(uint32_t dst, uint32_t src,
                                                  uint32_t bytes, uint32_t rmbar) {
    asm volatile("cp.async.bulk.shared::cluster.shared::cta.mbarrier::complete_tx::bytes "
                 "[%0], [%1], %2, [%3];"
                 :: "r"(dst), "r"(src), "r"(bytes), "r"(rmbar) : "memory");
}
__device__ __forceinline__ void fence_async_() {
    asm volatile("fence.proxy.async.shared::cta;" ::: "memory");
}
__device__ __forceinline__ void cluster_sync_() {
    asm volatile("barrier.cluster.arrive.aligned;" ::: "memory");
    asm volatile("barrier.cluster.wait.aligned;" ::: "memory");
}

__global__ void __launch_bounds__(256, 1) __cluster_dims__(8, 1, 1)
lstm_kernel(const float* __restrict__ xz, const float* __restrict__ rec,
            float* __restrict__ hs)
{
    __shared__ alignas(16) float h_sh[2][2][256];   // [phase][batch][unit]
    __shared__ alignas(16) float stage[2][2][32];   // [phase][batch][unit_loc]
    __shared__ alignas(8)  unsigned long long mbar_sh[2];

    const int tid  = threadIdx.x;
    const int lane = tid & 31;
    const int wrp  = tid >> 5;      // 0..7
    const int gc   = tid >> 1;      // 0..127
    const int kh   = tid & 1;
    const int gate = gc & 3;
    const int uloc = gc >> 2;       // 0..31

    uint32_t rank;
    asm("mov.u32 %0, %%cluster_ctarank;" : "=r"(rank));
    const int b0   = (blockIdx.x >> 3) * 2;
    const int gcol = gate * 256 + (int)rank * 32 + uloc;

    // ---- weights: 128 k values, packed as 64 f32x2 regs (128 registers) ----
    unsigned long long w2[64];
    #pragma unroll
    for (int q = 0; q < 64; q++) {
        float wl = rec[(size_t)(kh * 128 + 2 * q + 0) * FOURU + gcol];
        float wh = rec[(size_t)(kh * 128 + 2 * q + 1) * FOURU + gcol];
        w2[q] = pack2(wl, wh);
    }

    // ---- init ----
    for (int i = tid; i < 2 * 2 * 256; i += 256) ((float*)h_sh)[i] = 0.f;
    uint32_t mbar_a  = (uint32_t)__cvta_generic_to_shared(&mbar_sh[0]);
    uint32_t hsh_a   = (uint32_t)__cvta_generic_to_shared(&h_sh[0][0][0]);
    uint32_t stage_a = (uint32_t)__cvta_generic_to_shared(&stage[0][0][0]);
    if (tid == 0) { mbar_init(mbar_a, 1); mbar_init(mbar_a + 8, 1); }
    __syncthreads();
    cluster_sync_();

    float cc  = 0.f;
    int par0 = 0, par1 = 0;

    float xz0 = __ldg(&xz[((size_t)(b0 + 0) * TT) * FOURU + gcol]);
    float xz1 = __ldg(&xz[((size_t)(b0 + 1) * TT) * FOURU + gcol]);

    for (int t = 0; t < TT; t++) {
        const int pp = t & 1;
        const int np = pp ^ 1;

        if (tid == 0 && t > 0) {
            int par = pp ? par1 : par0;
            mbar_wait(mbar_a + 8u * pp, par);
            if (pp) par1 ^= 1; else par0 ^= 1;
        }
        __syncthreads();

        // ---- dot product: 128 k (this half), both batches ----
        unsigned long long a0 = 0ull, a1 = 0ull, a2 = 0ull, a3 = 0ull;
        const ulonglong2* H0 = reinterpret_cast<const ulonglong2*>(&h_sh[pp][0][kh * 128]);
        const ulonglong2* H1 = reinterpret_cast<const ulonglong2*>(&h_sh[pp][1][kh * 128]);
        #pragma unroll
        for (int q = 0; q < 32; q++) {
            ulonglong2 u0 = H0[q];
            ulonglong2 u1 = H1[q];
            a0 = fma2(w2[2 * q + 0], u0.x, a0);
            a1 = fma2(w2[2 * q + 1], u0.y, a1);
            a2 = fma2(w2[2 * q + 0], u1.x, a2);
            a3 = fma2(w2[2 * q + 1], u1.y, a3);
        }
        float z0 = (lo32(a0) + hi32(a0)) + (lo32(a1) + hi32(a1));
        float z1 = (lo32(a2) + hi32(a2)) + (lo32(a3) + hi32(a3));
        z0 += __shfl_xor_sync(0xffffffffu, z0, 1);
        z1 += __shfl_xor_sync(0xffffffffu, z1, 1);
        z0 += xz0;
        z1 += xz1;

        // prefetch next xz (full step of slack)
        float nxz0 = 0.f, nxz1 = 0.f;
        if (t + 1 < TT) {
            nxz0 = __ldg(&xz[((size_t)(b0 + 0) * TT + (t + 1)) * FOURU + gcol]);
            nxz1 = __ldg(&xz[((size_t)(b0 + 1) * TT + (t + 1)) * FOURU + gcol]);
        }

        // ---- redistribute: lane = u*8 + b*4 + g gets z_b for (unit u, gate g)
        int src = (lane & 24) | ((lane & 3) << 1);
        float za = __shfl_sync(0xffffffffu, z0, src);
        float zb = __shfl_sync(0xffffffffu, z1, src);
        float zz = (lane & 4) ? zb : za;
        bool  isG = ((lane & 3) == 2);
        float s  = isG ? (-2.f * zz) : (-zz);
        float e  = __expf(s);
        float r  = __fdividef(1.f, 1.f + e);
        float gv = isG ? (2.f * r - 1.f) : r;   // tanh for g-gate, sigmoid else

        // ---- gather per (u,b) group, update c (replicated in 4 lanes) ----
        int base = lane & ~3;
        float iv = __shfl_sync(0xffffffffu, gv, base);
        float fv = __shfl_sync(0xffffffffu, gv, base | 1);
        float gg = __shfl_sync(0xffffffffu, gv, base | 2);
        float ov = __shfl_sync(0xffffffffu, gv, base | 3);
        cc = fmaf(fv, cc, iv * gg);
        float e2 = __expf(-2.f * cc);
        float th = __fdividef(2.f, 1.f + e2) - 1.f;
        float hv = ov * th;

        if ((lane & 3) == 0) {
            int u_out = (wrp << 2) | (lane >> 3);      // 0..31
            int b     = (lane >> 2) & 1;
            hs[((size_t)(b0 + b) * TT + t) * UU + (int)rank * 32 + u_out] = hv;
            stage[np][b][u_out] = hv;
        }
        xz0 = nxz0;
        xz1 = nxz1;
        __syncthreads();

        if (tid == 0 && t + 1 < TT)
            mbar_expect_tx(mbar_a + 8u * np, 2048);

        // ---- 16 bulk 128B copies: (peer, batch) per lane ----
        if (wrp == 0 && lane < 16 && t + 1 < TT) {
            fence_async_();
            uint32_t peer = (uint32_t)(lane >> 1);
            uint32_t b    = (uint32_t)(lane & 1);
            uint32_t srcs = stage_a + (uint32_t)np * 256u + b * 128u;
            uint32_t dstl = hsh_a + (uint32_t)np * 2048u + b * 1024u + rank * 128u;
            bulk_smem_cluster(mapa_(dstl, peer), srcs, 128u, mapa_(mbar_a + 8u * np, peer));
        }
    }
    cluster_sync_();
}

// ---------------------------------------------------------------------------
extern "C" void kernel_launch(void* const* d_in, const int* in_sizes, int n_in,
                              void* d_out, int out_size)
{
    const float* x      = (const float*)d_in[0];
    const float* w_in   = (const float*)d_in[1];
    const float* b_in   = (const float*)d_in[2];
    const float* kern   = (const float*)d_in[3];
    const float* rec    = (const float*)d_in[4];
    const float* bias   = (const float*)d_in[5];
    const float* w_out  = (const float*)d_in[6];
    const float* b_out  = (const float*)d_in[7];
    float* out = (float*)d_out;

    float *xin, *xz, *hs;
    cudaGetSymbolAddress((void**)&xin, g_xin);
    cudaGetSymbolAddress((void**)&xz,  g_xz);
    cudaGetSymbolAddress((void**)&hs,  g_hs);

    gemm_bias_kernel<<<dim3(DD / 64, MTOT / 128), 256>>>(x, w_in, b_in, xin,
                                                         MTOT, DD, CC);
    gemm_bias_kernel<<<dim3(FOURU / 64, MTOT / 128), 256>>>(xin, kern, bias, xz,
                                                            MTOT, FOURU, DD);
    lstm_kernel<<<128, 256>>>(xz, rec, hs);
    gemm_bias_kernel<<<dim3(UU / 64, MTOT / 128), 256>>>(hs, w_out, b_out, out,
                                                         MTOT, UU, UU);
}

// round 6
// speedup vs baseline: 1.2165x; 1.2165x over previous
#include <cuda_runtime.h>
#include <cstdint>

#define BB 32
#define TT 1024
#define CC 512
#define DD 256
#define UU 256
#define FOURU 1024
#define MTOT (BB*TT)

__device__ float g_xin[(size_t)MTOT * DD];
__device__ float g_xz [(size_t)MTOT * FOURU];
__device__ float g_hs [(size_t)MTOT * UU];

// ---------------- f32x2 helpers ----------------
__device__ __forceinline__ unsigned long long fma2(unsigned long long a,
                                                   unsigned long long b,
                                                   unsigned long long c) {
    unsigned long long d;
    asm("fma.rn.f32x2 %0, %1, %2, %3;" : "=l"(d) : "l"(a), "l"(b), "l"(c));
    return d;
}
__device__ __forceinline__ unsigned long long pack2(float lo, float hi) {
    unsigned long long d;
    asm("mov.b64 %0, {%1, %2};" : "=l"(d) : "r"(__float_as_uint(lo)), "r"(__float_as_uint(hi)));
    return d;
}
__device__ __forceinline__ float lo32(unsigned long long v) {
    return __uint_as_float((unsigned)(v & 0xffffffffull));
}
__device__ __forceinline__ float hi32(unsigned long long v) {
    return __uint_as_float((unsigned)(v >> 32));
}

// ---------------------------------------------------------------------------
// GEMM with bias, f32x2 inner product. BM=128, BN=64, BK=16, 256 thr, 8x4.
// (unchanged from best round)
// ---------------------------------------------------------------------------
__global__ void __launch_bounds__(256)
gemm_bias_kernel(const float* __restrict__ A, const float* __restrict__ B,
                 const float* __restrict__ bias, float* __restrict__ C,
                 int M, int N, int K)
{
    __shared__ float As[16][132];
    __shared__ float Bs[16][64];

    const int tid = threadIdx.x;
    const int tx = tid & 15;
    const int ty = tid >> 4;
    const int bm = blockIdx.y * 128;
    const int bn = blockIdx.x * 64;

    unsigned long long acc2[4][4];
    #pragma unroll
    for (int i = 0; i < 4; i++)
        #pragma unroll
        for (int j = 0; j < 4; j++) acc2[i][j] = 0ull;

    for (int k0 = 0; k0 < K; k0 += 16) {
        #pragma unroll
        for (int l = 0; l < 2; l++) {
            int id = tid + 256 * l;
            int r  = id >> 2;
            int c4 = id & 3;
            float4 v = *(const float4*)&A[(size_t)(bm + r) * K + k0 + c4 * 4];
            As[c4*4+0][r] = v.x;
            As[c4*4+1][r] = v.y;
            As[c4*4+2][r] = v.z;
            As[c4*4+3][r] = v.w;
        }
        {
            int r  = tid >> 4;
            int c4 = tid & 15;
            float4 v = *(const float4*)&B[(size_t)(k0 + r) * N + bn + c4 * 4];
            *(float4*)&Bs[r][c4 * 4] = v;
        }
        __syncthreads();

        #pragma unroll
        for (int kk = 0; kk < 16; kk++) {
            const ulonglong2* ap = reinterpret_cast<const ulonglong2*>(&As[kk][ty * 8]);
            ulonglong2 aA = ap[0];
            ulonglong2 aB = ap[1];
            float4 bf = *(const float4*)&Bs[kk][tx * 4];
            unsigned long long bd[4];
            bd[0] = pack2(bf.x, bf.x);
            bd[1] = pack2(bf.y, bf.y);
            bd[2] = pack2(bf.z, bf.z);
            bd[3] = pack2(bf.w, bf.w);
            #pragma unroll
            for (int j = 0; j < 4; j++) {
                acc2[0][j] = fma2(aA.x, bd[j], acc2[0][j]);
                acc2[1][j] = fma2(aA.y, bd[j], acc2[1][j]);
                acc2[2][j] = fma2(aB.x, bd[j], acc2[2][j]);
                acc2[3][j] = fma2(aB.y, bd[j], acc2[3][j]);
            }
        }
        __syncthreads();
    }

    float bv[4];
    #pragma unroll
    for (int j = 0; j < 4; j++) bv[j] = bias[bn + tx * 4 + j];

    #pragma unroll
    for (int ip = 0; ip < 4; ip++) {
        float4 o0, o1;
        o0.x = lo32(acc2[ip][0]) + bv[0];
        o0.y = lo32(acc2[ip][1]) + bv[1];
        o0.z = lo32(acc2[ip][2]) + bv[2];
        o0.w = lo32(acc2[ip][3]) + bv[3];
        o1.x = hi32(acc2[ip][0]) + bv[0];
        o1.y = hi32(acc2[ip][1]) + bv[1];
        o1.z = hi32(acc2[ip][2]) + bv[2];
        o1.w = hi32(acc2[ip][3]) + bv[3];
        *(float4*)&C[(size_t)(bm + ty * 8 + ip * 2 + 0) * N + bn + tx * 4] = o0;
        *(float4*)&C[(size_t)(bm + ty * 8 + ip * 2 + 1) * N + bn + tx * 4] = o1;
    }
}

// ---------------------------------------------------------------------------
// LSTM recurrence: 16 clusters x 8 CTAs, 512 thr/CTA (round-2 compute layout).
// A/B change vs round 2: per-step wait is tid0-only with acquire.CTA scope;
// release to the block via __syncthreads. No cluster-scope acquire, no
// cluster barrier, no bulk-copy engine inside the loop.
// ---------------------------------------------------------------------------
__device__ __forceinline__ uint32_t mapa_(uint32_t addr, uint32_t rank) {
    uint32_t r;
    asm("mapa.shared::cluster.u32 %0, %1, %2;" : "=r"(r) : "r"(addr), "r"(rank));
    return r;
}
__device__ __forceinline__ void st_async_f32(uint32_t rdata, float v, uint32_t rmbar) {
    asm volatile("st.async.shared::cluster.mbarrier::complete_tx::bytes.b32 [%0], %1, [%2];"
                 :: "r"(rdata), "r"(__float_as_uint(v)), "r"(rmbar) : "memory");
}
__device__ __forceinline__ void mbar_init(uint32_t addr, uint32_t cnt) {
    asm volatile("mbarrier.init.shared.b64 [%0], %1;" :: "r"(addr), "r"(cnt) : "memory");
}
__device__ __forceinline__ void mbar_expect_tx(uint32_t addr, uint32_t tx) {
    asm volatile("mbarrier.arrive.expect_tx.shared.b64 _, [%0], %1;"
                 :: "r"(addr), "r"(tx) : "memory");
}
__device__ __forceinline__ void mbar_wait_cta(uint32_t addr, uint32_t parity) {
    uint32_t done;
    asm volatile("{\n\t.reg .pred p;\n\t"
                 "mbarrier.try_wait.parity.acquire.cta.shared::cta.b64 p, [%1], %2, 0x989680;\n\t"
                 "selp.b32 %0, 1, 0, p;\n\t}"
                 : "=r"(done) : "r"(addr), "r"(parity) : "memory");
    while (!done) {
        asm volatile("{\n\t.reg .pred p;\n\t"
                     "mbarrier.try_wait.parity.acquire.cta.shared::cta.b64 p, [%1], %2, 0x989680;\n\t"
                     "selp.b32 %0, 1, 0, p;\n\t}"
                     : "=r"(done) : "r"(addr), "r"(parity) : "memory");
    }
}
__device__ __forceinline__ void cluster_sync_() {
    asm volatile("barrier.cluster.arrive.aligned;" ::: "memory");
    asm volatile("barrier.cluster.wait.aligned;" ::: "memory");
}
__device__ __forceinline__ float sigf(float x) {
    return __fdividef(1.f, 1.f + __expf(-x));
}
__device__ __forceinline__ float tanhfast(float x) {
    return __fdividef(2.f, 1.f + __expf(-2.f * x)) - 1.f;
}

__global__ void __launch_bounds__(512, 1) __cluster_dims__(8, 1, 1)
lstm_kernel(const float* __restrict__ xz, const float* __restrict__ rec,
            float* __restrict__ hs)
{
    __shared__ float h_sh[2][2][256];            // [phase][batch][unit]
    __shared__ float part[2][3][2][128];         // [phase][kg-1][batch][col]
    __shared__ alignas(8) unsigned long long mbar_sh[2];

    const int tid  = threadIdx.x;
    const int col  = tid & 127;
    const int kg   = tid >> 7;                   // 0..3
    const int gate = col & 3;
    const int unit = col >> 2;

    uint32_t rank;
    asm("mov.u32 %0, %%cluster_ctarank;" : "=r"(rank));
    const int b0 = (blockIdx.x >> 3) * 2;
    const int gcol = gate * 256 + (int)rank * 32 + unit;   // column in [0,1024)

    // weights: k in [kg*64, kg*64+64), packed into 32 f32x2 regs (64 regs)
    unsigned long long w2[32];
    #pragma unroll
    for (int q = 0; q < 32; q++) {
        float wl = rec[(size_t)(kg * 64 + 2 * q + 0) * FOURU + gcol];
        float wh = rec[(size_t)(kg * 64 + 2 * q + 1) * FOURU + gcol];
        w2[q] = pack2(wl, wh);
    }

    // init
    for (int i = tid; i < 2 * 2 * 256; i += 512) ((float*)h_sh)[i] = 0.f;
    uint32_t mbar_addr0 = (uint32_t)__cvta_generic_to_shared(&mbar_sh[0]);
    if (tid == 0) {
        mbar_init(mbar_addr0, 1);
        mbar_init(mbar_addr0 + 8, 1);
    }
    __syncthreads();
    cluster_sync_();   // mbar init + h_sh zeros visible cluster-wide

    float c0 = 0.f, c1 = 0.f;
    float xz0 = 0.f, xz1 = 0.f;
    if (kg == 0) {
        xz0 = __ldg(&xz[((size_t)(b0 + 0) * TT + 0) * FOURU + gcol]);
        xz1 = __ldg(&xz[((size_t)(b0 + 1) * TT + 0) * FOURU + gcol]);
    }

    uint32_t ldata = (uint32_t)__cvta_generic_to_shared(&h_sh[0][0][(int)rank * 32 + unit]);
    const uint32_t HPHASE = 2 * 256 * 4;   // bytes between phase buffers
    const uint32_t HBATCH = 256 * 4;       // bytes between batches

    int par0 = 0, par1 = 0;                // parities, only meaningful in tid0

    for (int t = 0; t < TT; t++) {
        const int pp = t & 1;

        // ---- wait for h(t-1): tid0 only, CTA-scope acquire; block release ----
        if (t > 0) {
            if (tid == 0) {
                int par = pp ? par1 : par0;
                mbar_wait_cta(mbar_addr0 + 8u * pp, par);
                if (pp) par1 ^= 1; else par0 ^= 1;
            }
            __syncthreads();
        }
        if (tid == 0 && t + 1 < TT)
            mbar_expect_tx(mbar_addr0 + 8u * (pp ^ 1), 2048);

        // ---- phase A: f32x2 dot over this thread's 64 k's, both batches ----
        unsigned long long a0 = 0ull, a1 = 0ull, a2 = 0ull, a3 = 0ull;
        const ulonglong2* h0p = reinterpret_cast<const ulonglong2*>(&h_sh[pp][0][kg * 64]);
        const ulonglong2* h1p = reinterpret_cast<const ulonglong2*>(&h_sh[pp][1][kg * 64]);
        #pragma unroll
        for (int q = 0; q < 16; q++) {
            ulonglong2 hv0 = h0p[q];
            ulonglong2 hv1 = h1p[q];
            a0 = fma2(w2[2 * q + 0], hv0.x, a0);
            a1 = fma2(w2[2 * q + 1], hv0.y, a1);
            a2 = fma2(w2[2 * q + 0], hv1.x, a2);
            a3 = fma2(w2[2 * q + 1], hv1.y, a3);
        }
        float s0 = (lo32(a0) + hi32(a0)) + (lo32(a1) + hi32(a1));
        float s1 = (lo32(a2) + hi32(a2)) + (lo32(a3) + hi32(a3));

        if (kg > 0) {
            part[pp][kg - 1][0][col] = s0;
            part[pp][kg - 1][1][col] = s1;
        }

        // prefetch next xz while partials settle
        float nxz0 = 0.f, nxz1 = 0.f;
        if (kg == 0 && t + 1 < TT) {
            nxz0 = __ldg(&xz[((size_t)(b0 + 0) * TT + (t + 1)) * FOURU + gcol]);
            nxz1 = __ldg(&xz[((size_t)(b0 + 1) * TT + (t + 1)) * FOURU + gcol]);
        }
        __syncthreads();

        if (kg == 0) {
            float z0 = s0 + part[pp][0][0][col] + part[pp][1][0][col]
                          + part[pp][2][0][col] + xz0;
            float z1 = s1 + part[pp][0][1][col] + part[pp][1][1][col]
                          + part[pp][2][1][col] + xz1;

            const int lane = tid & 31;
            const int base = lane & ~3;
            float zi0 = __shfl_sync(0xffffffffu, z0, base + 0);
            float zf0 = __shfl_sync(0xffffffffu, z0, base + 1);
            float zg0 = __shfl_sync(0xffffffffu, z0, base + 2);
            float zo0 = __shfl_sync(0xffffffffu, z0, base + 3);
            float zi1 = __shfl_sync(0xffffffffu, z1, base + 0);
            float zf1 = __shfl_sync(0xffffffffu, z1, base + 1);
            float zg1 = __shfl_sync(0xffffffffu, z1, base + 2);
            float zo1 = __shfl_sync(0xffffffffu, z1, base + 3);

            c0 = sigf(zf0) * c0 + sigf(zi0) * tanhfast(zg0);
            c1 = sigf(zf1) * c1 + sigf(zi1) * tanhfast(zg1);
            float h0v = sigf(zo0) * tanhfast(c0);
            float h1v = sigf(zo1) * tanhfast(c1);

            if (gate == 0) {
                hs[((size_t)(b0 + 0) * TT + t) * UU + (int)rank * 32 + unit] = h0v;
                hs[((size_t)(b0 + 1) * TT + t) * UU + (int)rank * 32 + unit] = h1v;
                if (t + 1 < TT) {
                    const int np = pp ^ 1;
                    uint32_t lbase = ldata + (uint32_t)np * HPHASE;
                    uint32_t lmb   = mbar_addr0 + 8u * np;
                    #pragma unroll
                    for (uint32_t p = 0; p < 8; p++) {
                        uint32_t rd = mapa_(lbase, p);
                        uint32_t rm = mapa_(lmb, p);
                        st_async_f32(rd, h0v, rm);
                        st_async_f32(rd + HBATCH, h1v, rm);
                    }
                }
            }
            xz0 = nxz0;
            xz1 = nxz1;
        }
    }
    cluster_sync_();   // don't exit while peers' st.async may target us
}

// ---------------------------------------------------------------------------
extern "C" void kernel_launch(void* const* d_in, const int* in_sizes, int n_in,
                              void* d_out, int out_size)
{
    const float* x      = (const float*)d_in[0];
    const float* w_in   = (const float*)d_in[1];
    const float* b_in   = (const float*)d_in[2];
    const float* kern   = (const float*)d_in[3];
    const float* rec    = (const float*)d_in[4];
    const float* bias   = (const float*)d_in[5];
    const float* w_out  = (const float*)d_in[6];
    const float* b_out  = (const float*)d_in[7];
    float* out = (float*)d_out;

    float *xin, *xz, *hs;
    cudaGetSymbolAddress((void**)&xin, g_xin);
    cudaGetSymbolAddress((void**)&xz,  g_xz);
    cudaGetSymbolAddress((void**)&hs,  g_hs);

    gemm_bias_kernel<<<dim3(DD / 64, MTOT / 128), 256>>>(x, w_in, b_in, xin,
                                                         MTOT, DD, CC);
    gemm_bias_kernel<<<dim3(FOURU / 64, MTOT / 128), 256>>>(xin, kern, bias, xz,
                                                            MTOT, FOURU, DD);
    lstm_kernel<<<128, 512>>>(xz, rec, hs);
    gemm_bias_kernel<<<dim3(UU / 64, MTOT / 128), 256>>>(hs, w_out, b_out, out,
                                                         MTOT, UU, UU);
}